// round 11
// baseline (speedup 1.0000x reference)
#include <cuda_runtime.h>
#include <cuda_fp16.h>
#include <cstdint>
#include <cstddef>

#define BB   16
#define CIN  256
#define COUT 256
#define HH   64
#define WW   64
#define LATD 512

typedef unsigned long long ull;

// ---------------- device scratch (static, no runtime allocation) ----------------
__device__ float g_s[BB * CIN];
__device__ float g_d[BB * COUT];
__device__ float g_w2[COUT * CIN];
// Winograd-transformed weights: [t16][cic][co 256][64 ci]  (pre-swizzled units)
__device__ __half g_U[16 * 4 * 256 * 64];
// Winograd-transformed modulated input: [t16][cic][b*1024+tile][64 ci] (pre-swizzled)
__device__ __half g_V[(size_t)16 * 4 * 16384 * 64];

// ---------------- prep kernels ----------------
__global__ void compute_s_kernel(const float* __restrict__ style,
                                 const float* __restrict__ style_w,
                                 const float* __restrict__ style_b) {
    int b = blockIdx.x, ci = threadIdx.x;
    float acc = style_b[ci];
    const float* srow = style + b * LATD;
#pragma unroll 4
    for (int l = 0; l < LATD; ++l)
        acc = fmaf(srow[l], style_w[l * CIN + ci], acc);
    g_s[b * CIN + ci] = acc;
}

// U = G w G^T per (co,ci); also w2 for demod. Pre-swizzle ci units by (co&7).
__global__ void wino_w_kernel(const float* __restrict__ weight) {
    int co = blockIdx.x, ci = threadIdx.x;
    const float* wp = weight + (co * CIN + ci) * 9;
    float w[3][3];
    float ssq = 0.f;
#pragma unroll
    for (int k = 0; k < 9; ++k) {
        float v = wp[k];
        ssq = fmaf(v, v, ssq);
        w[k / 3][k % 3] = v;
    }
    g_w2[co * CIN + ci] = ssq;
    // gw = G w  (4x3)
    float gw[4][3];
#pragma unroll
    for (int c = 0; c < 3; ++c) {
        gw[0][c] = w[0][c];
        gw[1][c] = 0.5f * (w[0][c] + w[1][c] + w[2][c]);
        gw[2][c] = 0.5f * (w[0][c] - w[1][c] + w[2][c]);
        gw[3][c] = w[2][c];
    }
    int cic = ci >> 6, cil = ci & 63;
    int cil_sw = (((cil >> 3) ^ (co & 7)) << 3) | (cil & 7);
#pragma unroll
    for (int r = 0; r < 4; ++r) {
        float u0 = gw[r][0];
        float u1 = 0.5f * (gw[r][0] + gw[r][1] + gw[r][2]);
        float u2 = 0.5f * (gw[r][0] - gw[r][1] + gw[r][2]);
        float u3 = gw[r][2];
        float uu[4] = {u0, u1, u2, u3};
#pragma unroll
        for (int cc = 0; cc < 4; ++cc) {
            int t16 = r * 4 + cc;
            g_U[((size_t)(t16 * 4 + cic) * 256 + co) * 64 + cil_sw] =
                __float2half_rn(uu[cc]);
        }
    }
}

__global__ void compute_d_kernel() {
    int b = blockIdx.x, co = threadIdx.x;
    const float* srow = g_s + b * CIN;
    const float* w2row = g_w2 + co * CIN;
    float acc = 0.f;
#pragma unroll 4
    for (int ci = 0; ci < CIN; ++ci) {
        float s = srow[ci];
        acc = fmaf(s * s, w2row[ci], acc);
    }
    g_d[b * COUT + co] = rsqrtf(acc + 1e-8f);
}

// ---------------- input transform: V = B^T (s*x) B ----------------
// block = (b, tile-row th, ci-block of 32). smem: xin fp32 halo rows + vst staging.
#define VT_XIN_PITCH 68
#define VT_VST_PITCH 40
#define VT_SMEM (32 * 4 * VT_XIN_PITCH * 4 + 16 * 32 * VT_VST_PITCH * 2)

__global__ void __launch_bounds__(256) vtrans_kernel(const float* __restrict__ x) {
    extern __shared__ __align__(16) char smraw[];
    float* xin = (float*)smraw;                                   // [32ci][4r][68]
    __half* vst = (__half*)(smraw + 32 * 4 * VT_XIN_PITCH * 4);   // [16t][32tw][40]

    int blk = blockIdx.x;
    int cib = blk & 7, th = (blk >> 3) & 31, b = blk >> 8;
    int t = threadIdx.x;

    // zero w-halo columns (col 0 = w=-1, col 65 = w=64)
    if (t < 128) {
        int cil = t >> 2, rr = t & 3;
        xin[(cil * 4 + rr) * VT_XIN_PITCH + 0] = 0.f;
        xin[(cil * 4 + rr) * VT_XIN_PITCH + 65] = 0.f;
    }
    // load 4 halo rows x 64 w x 32 ci (coalesced)
#pragma unroll
    for (int j = 0; j < 32; ++j) {
        int idx = t + 256 * j;
        int w = idx & 63, rr = (idx >> 6) & 3, cil = idx >> 8;
        int hh = 2 * th - 1 + rr;
        float v = 0.f;
        if ((unsigned)hh < 64u)
            v = x[((size_t)(b * CIN + cib * 32 + cil) * HH + hh) * WW + w];
        xin[(cil * 4 + rr) * VT_XIN_PITCH + w + 1] = v;
    }
    __syncthreads();

    // transform: 32 tiles x 32 ci, 4 items per thread
#pragma unroll
    for (int q = 0; q < 4; ++q) {
        int item = t + 256 * q;
        int tw = item & 31, cil = item >> 5;
        float s = g_s[b * CIN + cib * 32 + cil];
        float d[4][4];
#pragma unroll
        for (int r = 0; r < 4; ++r)
#pragma unroll
            for (int c = 0; c < 4; ++c)
                d[r][c] = xin[(cil * 4 + r) * VT_XIN_PITCH + 2 * tw + c];
        float e[4][4];
#pragma unroll
        for (int c = 0; c < 4; ++c) {
            e[0][c] = d[0][c] - d[2][c];
            e[1][c] = d[1][c] + d[2][c];
            e[2][c] = d[2][c] - d[1][c];
            e[3][c] = d[1][c] - d[3][c];
        }
#pragma unroll
        for (int r = 0; r < 4; ++r) {
            float v0 = e[r][0] - e[r][2];
            float v1 = e[r][1] + e[r][2];
            float v2 = e[r][2] - e[r][1];
            float v3 = e[r][1] - e[r][3];
            vst[((r * 4 + 0) * 32 + tw) * VT_VST_PITCH + cil] = __float2half_rn(v0 * s);
            vst[((r * 4 + 1) * 32 + tw) * VT_VST_PITCH + cil] = __float2half_rn(v1 * s);
            vst[((r * 4 + 2) * 32 + tw) * VT_VST_PITCH + cil] = __float2half_rn(v2 * s);
            vst[((r * 4 + 3) * 32 + tw) * VT_VST_PITCH + cil] = __float2half_rn(v3 * s);
        }
    }
    __syncthreads();

    // flush: 2048 uint4 units (16t x 32tw x 4 ci-units), swizzled, coalesced-ish
#pragma unroll
    for (int j = 0; j < 8; ++j) {
        int u = t + 256 * j;
        int ul = u & 3, tw = (u >> 2) & 31, t16 = u >> 7;
        uint4 v = ((const uint4*)(vst + (t16 * 32 + tw) * VT_VST_PITCH))[ul];
        int unit = ((cib & 1) << 2) + ul;
        int phys = unit ^ (tw & 7);
        size_t off = ((size_t)(t16 * 4 + (cib >> 1)) * 16384
                      + b * 1024 + th * 32 + tw) * 64 + phys * 8;
        *((uint4*)(g_V + off)) = v;
    }
}

// ---------------- ptx helpers ----------------
static __device__ __forceinline__ uint32_t s2u(const void* p) {
    uint32_t a;
    asm("{ .reg .u64 t; cvta.to.shared.u64 t, %1; cvt.u32.u64 %0, t; }" : "=r"(a) : "l"(p));
    return a;
}
static __device__ __forceinline__ void mbar_init(uint32_t m, uint32_t c) {
    asm volatile("mbarrier.init.shared.b64 [%0], %1;" :: "r"(m), "r"(c) : "memory");
}
static __device__ __forceinline__ void mbar_expect(uint32_t m, uint32_t bytes) {
    asm volatile("mbarrier.arrive.expect_tx.shared.b64 _, [%0], %1;"
                 :: "r"(m), "r"(bytes) : "memory");
}
static __device__ __forceinline__ void mbar_wait(uint32_t m, uint32_t ph) {
    asm volatile(
        "{\n\t.reg .pred P;\n\t"
        "WL_%=:\n\t"
        "mbarrier.try_wait.parity.acquire.cta.shared::cta.b64 P, [%0], %1, 0x989680;\n\t"
        "@!P bra WL_%=;\n\t}"
        :: "r"(m), "r"(ph) : "memory");
}
static __device__ __forceinline__ void bulk_g2s(uint32_t dst, const void* src,
                                                uint32_t bytes, uint32_t mbar) {
    asm volatile(
        "cp.async.bulk.shared::cluster.global.mbarrier::complete_tx::bytes "
        "[%0], [%1], %2, [%3];"
        :: "r"(dst), "l"(src), "r"(bytes), "r"(mbar) : "memory");
}
#define LDSM4(r0, r1, r2, r3, a) \
    asm volatile("ldmatrix.sync.aligned.m8n8.x4.shared.b16 {%0,%1,%2,%3}, [%4];" \
                 : "=r"(r0), "=r"(r1), "=r"(r2), "=r"(r3) : "r"(a))
#define MMA16816(c, a, b0, b1) \
    asm volatile("mma.sync.aligned.m16n8k16.row.col.f32.f16.f16.f32 " \
                 "{%0,%1,%2,%3}, {%4,%5,%6,%7}, {%8,%9}, {%0,%1,%2,%3};" \
                 : "+f"((c)[0]), "+f"((c)[1]), "+f"((c)[2]), "+f"((c)[3]) \
                 : "r"((a)[0]), "r"((a)[1]), "r"((a)[2]), "r"((a)[3]), "r"(b0), "r"(b1))

// ---------------- Winograd GEMM + fused output transform ----------------
// CTA: 64 px-tiles x 128 co. 8 warps = 2(m) x 4(n); warp tile 32 tiles x 32 co.
// Chunk = (tap, cic): A 64x64 fp16 = 8KB, B 128x64 fp16 = 16KB. 3 stages x 24KB.
#define ST_SZ    24576
#define SM_MBAR  (3 * ST_SZ)
#define SMEM_REQ (SM_MBAR + 64)
#define EPI_PITCH 67

static __device__ __forceinline__ void issue_chunk(uint32_t smb, int st, int cid,
                                                   int tiles0, int co0) {
    const int t16 = cid >> 2, cic = cid & 3;
    const uint32_t base = smb + st * ST_SZ;
    const uint32_t mbar = smb + SM_MBAR + st * 8;
    mbar_expect(mbar, 24576u);
    bulk_g2s(base, g_V + ((size_t)(t16 * 4 + cic) * 16384 + tiles0) * 64, 8192u, mbar);
    bulk_g2s(base + 8192, g_U + ((size_t)(t16 * 4 + cic) * 256 + co0) * 64, 16384u, mbar);
}

__global__ void __launch_bounds__(256, 1) wino_gemm_kernel(
    const float* __restrict__ noise,
    const float* __restrict__ bias,
    const float* __restrict__ nwp,
    float* __restrict__ out)
{
    extern __shared__ __align__(1024) char sm[];
    const uint32_t smb = s2u(sm);
    const int tid = threadIdx.x;
    const int lane = tid & 31, wid = tid >> 5;
    const int mw = wid & 1, nw = wid >> 1;
    const int tiles0 = blockIdx.x * 64;
    const int b = blockIdx.x >> 4;
    const int h0 = (blockIdx.x & 15) * 4;
    const int co0 = blockIdx.y * 128;

    if (tid == 0) {
        mbar_init(smb + SM_MBAR, 1);
        mbar_init(smb + SM_MBAR + 8, 1);
        mbar_init(smb + SM_MBAR + 16, 1);
    }
    __syncthreads();
    if (tid == 0) {
        issue_chunk(smb, 0, 0, tiles0, co0);
        issue_chunk(smb, 1, 1, tiles0, co0);
        issue_chunk(smb, 2, 2, tiles0, co0);
    }

    const int rA = mw * 32 + (lane & 15);          // + mi*16
    const int hiA = lane >> 4;
    const int rB = nw * 32 + (lane & 7) + ((lane >> 4) & 1) * 8;
    const int hiB = (lane >> 3) & 1;
    const int sx = lane & 7;

    float y[2][4][4][4] = {};
    int ph[3] = {0, 0, 0};

    for (int t16 = 0; t16 < 16; ++t16) {
        float m[2][4][4] = {};
#pragma unroll
        for (int cic = 0; cic < 4; ++cic) {
            const int cid = t16 * 4 + cic;
            const int s = cid % 3;
            mbar_wait(smb + SM_MBAR + s * 8, ph[s]);
            ph[s] ^= 1;
            const uint32_t stA = smb + s * ST_SZ;
            const uint32_t stB = stA + 8192;
#pragma unroll
            for (int ks = 0; ks < 4; ++ks) {
                uint32_t a[2][4], bw[4][2];
#pragma unroll
                for (int mi = 0; mi < 2; ++mi) {
                    uint32_t ad = stA + (uint32_t)(rA + mi * 16) * 128
                                + (uint32_t)(((ks * 2 + hiA) ^ sx) << 4);
                    LDSM4(a[mi][0], a[mi][1], a[mi][2], a[mi][3], ad);
                }
#pragma unroll
                for (int g = 0; g < 2; ++g) {
                    uint32_t bd = stB + (uint32_t)(rB + g * 16) * 128
                                + (uint32_t)(((ks * 2 + hiB) ^ sx) << 4);
                    LDSM4(bw[2 * g][0], bw[2 * g][1], bw[2 * g + 1][0], bw[2 * g + 1][1], bd);
                }
#pragma unroll
                for (int mi = 0; mi < 2; ++mi)
#pragma unroll
                    for (int ni = 0; ni < 4; ++ni)
                        MMA16816(m[mi][ni], a[mi], bw[ni][0], bw[ni][1]);
            }
            __syncthreads();
            if (tid == 0 && cid + 3 < 64)
                issue_chunk(smb, s, cid + 3, tiles0, co0);
        }
        // fold tap into 2x2 output-position accumulators (A^T coefs in {0,+-1})
        const int tY = t16 >> 2, tX = t16 & 3;
        const float cy0 = (tY != 3) ? 1.f : 0.f;
        const float cy1 = (tY == 0) ? 0.f : ((tY == 1) ? 1.f : -1.f);
        const float cx0 = (tX != 3) ? 1.f : 0.f;
        const float cx1 = (tX == 0) ? 0.f : ((tX == 1) ? 1.f : -1.f);
        const float c00 = cy0 * cx0, c01 = cy0 * cx1;
        const float c10 = cy1 * cx0, c11 = cy1 * cx1;
#pragma unroll
        for (int mi = 0; mi < 2; ++mi)
#pragma unroll
            for (int ni = 0; ni < 4; ++ni)
#pragma unroll
                for (int r = 0; r < 4; ++r) {
                    float mv = m[mi][ni][r];
                    y[mi][ni][r][0] += c00 * mv;
                    y[mi][ni][r][1] += c01 * mv;
                    y[mi][ni][r][2] += c10 * mv;
                    y[mi][ni][r][3] += c11 * mv;
                }
    }

    // ---- epilogue: two co-halves; smem gather -> fused coalesced stores ----
    float* smo = (float*)sm;
    const float nwv = nwp[0];
#pragma unroll 1
    for (int p = 0; p < 2; ++p) {
        if ((nw >> 1) == p) {
#pragma unroll
            for (int mi = 0; mi < 2; ++mi)
#pragma unroll
                for (int ni = 0; ni < 4; ++ni)
#pragma unroll
                    for (int r = 0; r < 4; ++r) {
                        int tile_l = mw * 32 + mi * 16 + (lane >> 2) + ((r >= 2) ? 8 : 0);
                        int co_l = (nw & 1) * 32 + ni * 8 + 2 * (lane & 3) + (r & 1);
                        int base = co_l * (4 * EPI_PITCH)
                                 + (2 * (tile_l >> 5)) * EPI_PITCH + 2 * (tile_l & 31);
#pragma unroll
                        for (int pos = 0; pos < 4; ++pos)
                            smo[base + (pos >> 1) * EPI_PITCH + (pos & 1)] =
                                y[mi][ni][r][pos];
                    }
        }
        __syncthreads();
#pragma unroll 4
        for (int it = 0; it < 32; ++it) {
            int row = wid + 8 * it;               // 0..255 = 64co x 4h
            int co_f = row >> 2, h_f = row & 3;
            int cog = co0 + p * 64 + co_f;
            float dv = g_d[b * COUT + cog];
            float bv = bias[cog];
            int w = 2 * lane;
            int hg = h0 + h_f;
            float v0 = smo[co_f * (4 * EPI_PITCH) + h_f * EPI_PITCH + w];
            float v1 = smo[co_f * (4 * EPI_PITCH) + h_f * EPI_PITCH + w + 1];
            float nz0 = noise[(b * HH + hg) * WW + w] * nwv;
            float nz1 = noise[(b * HH + hg) * WW + w + 1] * nwv;
            v0 = v0 * dv + nz0 + bv;
            v1 = v1 * dv + nz1 + bv;
            v0 = (v0 >= 0.f ? v0 : 0.2f * v0) * 1.4142135623730951f;
            v1 = (v1 >= 0.f ? v1 : 0.2f * v1) * 1.4142135623730951f;
            float2 o2 = make_float2(v0, v1);
            *(float2*)&out[((size_t)(b * COUT + cog) * HH + hg) * WW + w] = o2;
        }
        __syncthreads();
    }
}

// ---------------------------------------------------------------------------
extern "C" void kernel_launch(void* const* d_in, const int* in_sizes, int n_in,
                              void* d_out, int out_size) {
    const float* x       = (const float*)d_in[0];
    const float* style   = (const float*)d_in[1];
    const float* noise   = (const float*)d_in[2];
    const float* weight  = (const float*)d_in[3];
    const float* style_w = (const float*)d_in[4];
    const float* style_b = (const float*)d_in[5];
    const float* bias    = (const float*)d_in[6];
    const float* nw      = (const float*)d_in[7];
    float* out = (float*)d_out;

    cudaFuncSetAttribute(vtrans_kernel,
                         cudaFuncAttributeMaxDynamicSharedMemorySize, VT_SMEM);
    cudaFuncSetAttribute(wino_gemm_kernel,
                         cudaFuncAttributeMaxDynamicSharedMemorySize, SMEM_REQ);

    compute_s_kernel<<<BB, CIN>>>(style, style_w, style_b);
    wino_w_kernel<<<COUT, CIN>>>(weight);
    compute_d_kernel<<<BB, COUT>>>();
    vtrans_kernel<<<BB * 32 * 8, 256, VT_SMEM>>>(x);
    wino_gemm_kernel<<<dim3(256, 2), 256, SMEM_REQ>>>(noise, bias, nw, out);
}

// round 12
// speedup vs baseline: 1.0986x; 1.0986x over previous
#include <cuda_runtime.h>
#include <cuda_fp16.h>
#include <cstdint>
#include <cstddef>

#define BB   16
#define CIN  256
#define COUT 256
#define HH   64
#define WW   64
#define LATD 512

typedef unsigned long long ull;

// ---------------- device scratch (static, no runtime allocation) ----------------
__device__ float g_s[BB * CIN];
__device__ float g_d[BB * COUT];
__device__ float g_w2[COUT * CIN];
// Winograd-transformed weights: [t16][cic][co 256][64 ci]  (pre-swizzled units)
__device__ __half g_U[16 * 4 * 256 * 64];
// Winograd-transformed modulated input: [t16][cic][b*1024+tile][64 ci] (pre-swizzled)
__device__ __half g_V[(size_t)16 * 4 * 16384 * 64];

// ---------------- prep kernels ----------------
__global__ void compute_s_kernel(const float* __restrict__ style,
                                 const float* __restrict__ style_w,
                                 const float* __restrict__ style_b) {
    int b = blockIdx.x, ci = threadIdx.x;
    float acc = style_b[ci];
    const float* srow = style + b * LATD;
#pragma unroll 4
    for (int l = 0; l < LATD; ++l)
        acc = fmaf(srow[l], style_w[l * CIN + ci], acc);
    g_s[b * CIN + ci] = acc;
}

// U = G w G^T per (co,ci); also w2 for demod. Pre-swizzle ci units by (co&7).
__global__ void wino_w_kernel(const float* __restrict__ weight) {
    int co = blockIdx.x, ci = threadIdx.x;
    const float* wp = weight + (co * CIN + ci) * 9;
    float w[3][3];
    float ssq = 0.f;
#pragma unroll
    for (int k = 0; k < 9; ++k) {
        float v = wp[k];
        ssq = fmaf(v, v, ssq);
        w[k / 3][k % 3] = v;
    }
    g_w2[co * CIN + ci] = ssq;
    float gw[4][3];
#pragma unroll
    for (int c = 0; c < 3; ++c) {
        gw[0][c] = w[0][c];
        gw[1][c] = 0.5f * (w[0][c] + w[1][c] + w[2][c]);
        gw[2][c] = 0.5f * (w[0][c] - w[1][c] + w[2][c]);
        gw[3][c] = w[2][c];
    }
    int cic = ci >> 6, cil = ci & 63;
    int cil_sw = (((cil >> 3) ^ (co & 7)) << 3) | (cil & 7);
#pragma unroll
    for (int r = 0; r < 4; ++r) {
        float u0 = gw[r][0];
        float u1 = 0.5f * (gw[r][0] + gw[r][1] + gw[r][2]);
        float u2 = 0.5f * (gw[r][0] - gw[r][1] + gw[r][2]);
        float u3 = gw[r][2];
        float uu[4] = {u0, u1, u2, u3};
#pragma unroll
        for (int cc = 0; cc < 4; ++cc) {
            int t16 = r * 4 + cc;
            g_U[((size_t)(t16 * 4 + cic) * 256 + co) * 64 + cil_sw] =
                __float2half_rn(uu[cc]);
        }
    }
}

__global__ void compute_d_kernel() {
    int b = blockIdx.x, co = threadIdx.x;
    const float* srow = g_s + b * CIN;
    const float* w2row = g_w2 + co * CIN;
    float acc = 0.f;
#pragma unroll 4
    for (int ci = 0; ci < CIN; ++ci) {
        float s = srow[ci];
        acc = fmaf(s * s, w2row[ci], acc);
    }
    g_d[b * COUT + co] = rsqrtf(acc + 1e-8f);
}

// ---------------- input transform: V = B^T (s*x) B ----------------
// Conflict-free smem: fp32 staging with pitch 33 (lane stride 33 banks == 1).
#define VT_XP 66
#define VT_VP 33
#define VT_SMEM (32 * 4 * VT_XP * 4 + 16 * 32 * VT_VP * 4)

__global__ void __launch_bounds__(256) vtrans_kernel(const float* __restrict__ x) {
    extern __shared__ __align__(16) char smraw[];
    float* xin = (float*)smraw;                          // [32cil][4r][66]
    float* vst = (float*)(smraw + 32 * 4 * VT_XP * 4);   // [(t16*32+tw)*33 + cil]

    int blk = blockIdx.x;
    int cib = blk & 7, th = (blk >> 3) & 31, b = blk >> 8;
    int t = threadIdx.x;

    // zero w-halo columns (col 0 = w=-1, col 65 = w=64)
    if (t < 128) {
        int cil = t >> 2, rr = t & 3;
        xin[(cil * 4 + rr) * VT_XP + 0] = 0.f;
        xin[(cil * 4 + rr) * VT_XP + 65] = 0.f;
    }
    // load 4 halo rows x 64 w x 32 ci (coalesced)
#pragma unroll
    for (int j = 0; j < 32; ++j) {
        int idx = t + 256 * j;
        int w = idx & 63, rr = (idx >> 6) & 3, cil = idx >> 8;
        int hh = 2 * th - 1 + rr;
        float v = 0.f;
        if ((unsigned)hh < 64u)
            v = x[((size_t)(b * CIN + cib * 32 + cil) * HH + hh) * WW + w];
        xin[(cil * 4 + rr) * VT_XP + w + 1] = v;
    }
    __syncthreads();

    // transform: 32 tiles x 32 ci, 4 items per thread; float2 input loads
#pragma unroll
    for (int q = 0; q < 4; ++q) {
        int item = t + 256 * q;
        int tw = item & 31, cil = item >> 5;
        float s = g_s[b * CIN + cib * 32 + cil];
        const float2* x2 = (const float2*)xin;
        float d[4][4];
#pragma unroll
        for (int r = 0; r < 4; ++r) {
            int base2 = ((cil * 4 + r) * VT_XP) >> 1;
            float2 p0 = x2[base2 + tw];
            float2 p1 = x2[base2 + tw + 1];
            d[r][0] = p0.x; d[r][1] = p0.y; d[r][2] = p1.x; d[r][3] = p1.y;
        }
        float e[4][4];
#pragma unroll
        for (int c = 0; c < 4; ++c) {
            e[0][c] = d[0][c] - d[2][c];
            e[1][c] = d[1][c] + d[2][c];
            e[2][c] = d[2][c] - d[1][c];
            e[3][c] = d[1][c] - d[3][c];
        }
#pragma unroll
        for (int r = 0; r < 4; ++r) {
            float v0 = e[r][0] - e[r][2];
            float v1 = e[r][1] + e[r][2];
            float v2 = e[r][2] - e[r][1];
            float v3 = e[r][1] - e[r][3];
            vst[((r * 4 + 0) * 32 + tw) * VT_VP + cil] = v0 * s;
            vst[((r * 4 + 1) * 32 + tw) * VT_VP + cil] = v1 * s;
            vst[((r * 4 + 2) * 32 + tw) * VT_VP + cil] = v2 * s;
            vst[((r * 4 + 3) * 32 + tw) * VT_VP + cil] = v3 * s;
        }
    }
    __syncthreads();

    // flush: 2048 uint4 units; fp32->fp16 convert at flush; conflict-free reads
#pragma unroll
    for (int j = 0; j < 8; ++j) {
        int u = t + 256 * j;
        int ul = u & 3, tw = (u >> 2) & 31, t16 = u >> 7;
        const float* src = vst + (t16 * 32 + tw) * VT_VP + ul * 8;
        uint4 v;
        __half* hp = (__half*)&v;
#pragma unroll
        for (int k = 0; k < 8; ++k) hp[k] = __float2half_rn(src[k]);
        int unit = ((cib & 1) << 2) + ul;
        int phys = unit ^ (tw & 7);
        size_t off = ((size_t)(t16 * 4 + (cib >> 1)) * 16384
                      + b * 1024 + th * 32 + tw) * 64 + phys * 8;
        *((uint4*)(g_V + off)) = v;
    }
}

// ---------------- ptx helpers ----------------
static __device__ __forceinline__ uint32_t s2u(const void* p) {
    uint32_t a;
    asm("{ .reg .u64 t; cvta.to.shared.u64 t, %1; cvt.u32.u64 %0, t; }" : "=r"(a) : "l"(p));
    return a;
}
static __device__ __forceinline__ void mbar_init(uint32_t m, uint32_t c) {
    asm volatile("mbarrier.init.shared.b64 [%0], %1;" :: "r"(m), "r"(c) : "memory");
}
static __device__ __forceinline__ void mbar_expect(uint32_t m, uint32_t bytes) {
    asm volatile("mbarrier.arrive.expect_tx.shared.b64 _, [%0], %1;"
                 :: "r"(m), "r"(bytes) : "memory");
}
static __device__ __forceinline__ void mbar_wait(uint32_t m, uint32_t ph) {
    asm volatile(
        "{\n\t.reg .pred P;\n\t"
        "WL_%=:\n\t"
        "mbarrier.try_wait.parity.acquire.cta.shared::cta.b64 P, [%0], %1, 0x989680;\n\t"
        "@!P bra WL_%=;\n\t}"
        :: "r"(m), "r"(ph) : "memory");
}
static __device__ __forceinline__ void bulk_g2s(uint32_t dst, const void* src,
                                                uint32_t bytes, uint32_t mbar) {
    asm volatile(
        "cp.async.bulk.shared::cluster.global.mbarrier::complete_tx::bytes "
        "[%0], [%1], %2, [%3];"
        :: "r"(dst), "l"(src), "r"(bytes), "r"(mbar) : "memory");
}
#define LDSM4(r0, r1, r2, r3, a) \
    asm volatile("ldmatrix.sync.aligned.m8n8.x4.shared.b16 {%0,%1,%2,%3}, [%4];" \
                 : "=r"(r0), "=r"(r1), "=r"(r2), "=r"(r3) : "r"(a))
#define MMA16816(c, a, b0, b1) \
    asm volatile("mma.sync.aligned.m16n8k16.row.col.f32.f16.f16.f32 " \
                 "{%0,%1,%2,%3}, {%4,%5,%6,%7}, {%8,%9}, {%0,%1,%2,%3};" \
                 : "+f"((c)[0]), "+f"((c)[1]), "+f"((c)[2]), "+f"((c)[3]) \
                 : "r"((a)[0]), "r"((a)[1]), "r"((a)[2]), "r"((a)[3]), "r"(b0), "r"(b1))

// ---------------- Winograd GEMM + fused output transform ----------------
// CTA: 64 px-tiles x 128 co. Chunk = (t16, cic-pair): K=128.
// Stage 48KB: V0 8K @0, V1 8K @8K, U0 16K @16K, U1 16K @32K. 4 stages = 192KB.
#define ST_SZ    49152
#define SM_MBAR  (4 * ST_SZ)
#define SMEM_REQ (SM_MBAR + 64)
#define EPI_PITCH 67

static __device__ __forceinline__ void issue_chunk(uint32_t smb, int st, int cid,
                                                   int tiles0, int co0) {
    const int t16 = cid >> 1, cic0 = (cid & 1) * 2;
    const uint32_t base = smb + st * ST_SZ;
    const uint32_t mbar = smb + SM_MBAR + st * 8;
    mbar_expect(mbar, 49152u);
    bulk_g2s(base,
             g_V + ((size_t)(t16 * 4 + cic0) * 16384 + tiles0) * 64, 8192u, mbar);
    bulk_g2s(base + 8192,
             g_V + ((size_t)(t16 * 4 + cic0 + 1) * 16384 + tiles0) * 64, 8192u, mbar);
    bulk_g2s(base + 16384,
             g_U + ((size_t)(t16 * 4 + cic0) * 256 + co0) * 64, 16384u, mbar);
    bulk_g2s(base + 32768,
             g_U + ((size_t)(t16 * 4 + cic0 + 1) * 256 + co0) * 64, 16384u, mbar);
}

__global__ void __launch_bounds__(256, 1) wino_gemm_kernel(
    const float* __restrict__ noise,
    const float* __restrict__ bias,
    const float* __restrict__ nwp,
    float* __restrict__ out)
{
    extern __shared__ __align__(1024) char sm[];
    const uint32_t smb = s2u(sm);
    const int tid = threadIdx.x;
    const int lane = tid & 31, wid = tid >> 5;
    const int mw = wid & 1, nw = wid >> 1;
    const int tiles0 = blockIdx.x * 64;
    const int b = blockIdx.x >> 4;
    const int h0 = (blockIdx.x & 15) * 4;
    const int co0 = blockIdx.y * 128;

    if (tid == 0) {
        mbar_init(smb + SM_MBAR, 1);
        mbar_init(smb + SM_MBAR + 8, 1);
        mbar_init(smb + SM_MBAR + 16, 1);
        mbar_init(smb + SM_MBAR + 24, 1);
    }
    __syncthreads();
    if (tid == 0) {
        issue_chunk(smb, 0, 0, tiles0, co0);
        issue_chunk(smb, 1, 1, tiles0, co0);
        issue_chunk(smb, 2, 2, tiles0, co0);
    }

    const int rA = mw * 32 + (lane & 15);
    const int hiA = lane >> 4;
    const int rB = nw * 32 + (lane & 7) + ((lane >> 4) & 1) * 8;
    const int hiB = (lane >> 3) & 1;
    const int sx = lane & 7;

    float y[2][4][4][4] = {};
    int ph[4] = {0, 0, 0, 0};

    for (int t16 = 0; t16 < 16; ++t16) {
        float m[2][4][4] = {};
#pragma unroll
        for (int cp = 0; cp < 2; ++cp) {
            const int cid = t16 * 2 + cp;
            const int s = cid & 3;
            mbar_wait(smb + SM_MBAR + s * 8, ph[s]);
            ph[s] ^= 1;
            // stage (cid-1)&3 was freed by the syncthreads ending chunk cid-1
            if (tid == 0 && cid + 3 < 32)
                issue_chunk(smb, (cid + 3) & 3, cid + 3, tiles0, co0);
#pragma unroll
            for (int cc = 0; cc < 2; ++cc) {
                const uint32_t stA = smb + s * ST_SZ + cc * 8192;
                const uint32_t stB = smb + s * ST_SZ + 16384 + cc * 16384;
#pragma unroll
                for (int ks = 0; ks < 4; ++ks) {
                    uint32_t a[2][4], bw[4][2];
#pragma unroll
                    for (int mi = 0; mi < 2; ++mi) {
                        uint32_t ad = stA + (uint32_t)(rA + mi * 16) * 128
                                    + (uint32_t)(((ks * 2 + hiA) ^ sx) << 4);
                        LDSM4(a[mi][0], a[mi][1], a[mi][2], a[mi][3], ad);
                    }
#pragma unroll
                    for (int g = 0; g < 2; ++g) {
                        uint32_t bd = stB + (uint32_t)(rB + g * 16) * 128
                                    + (uint32_t)(((ks * 2 + hiB) ^ sx) << 4);
                        LDSM4(bw[2 * g][0], bw[2 * g][1],
                              bw[2 * g + 1][0], bw[2 * g + 1][1], bd);
                    }
#pragma unroll
                    for (int mi = 0; mi < 2; ++mi)
#pragma unroll
                        for (int ni = 0; ni < 4; ++ni)
                            MMA16816(m[mi][ni], a[mi], bw[ni][0], bw[ni][1]);
                }
            }
            __syncthreads();
        }
        // fold tap into 2x2 output-position accumulators (A^T coefs in {0,+-1})
        const int tY = t16 >> 2, tX = t16 & 3;
        const float cy0 = (tY != 3) ? 1.f : 0.f;
        const float cy1 = (tY == 0) ? 0.f : ((tY == 1) ? 1.f : -1.f);
        const float cx0 = (tX != 3) ? 1.f : 0.f;
        const float cx1 = (tX == 0) ? 0.f : ((tX == 1) ? 1.f : -1.f);
        const float c00 = cy0 * cx0, c01 = cy0 * cx1;
        const float c10 = cy1 * cx0, c11 = cy1 * cx1;
#pragma unroll
        for (int mi = 0; mi < 2; ++mi)
#pragma unroll
            for (int ni = 0; ni < 4; ++ni)
#pragma unroll
                for (int r = 0; r < 4; ++r) {
                    float mv = m[mi][ni][r];
                    y[mi][ni][r][0] += c00 * mv;
                    y[mi][ni][r][1] += c01 * mv;
                    y[mi][ni][r][2] += c10 * mv;
                    y[mi][ni][r][3] += c11 * mv;
                }
    }

    // ---- epilogue: two co-halves; smem gather -> fused coalesced stores ----
    float* smo = (float*)sm;
    const float nwv = nwp[0];
#pragma unroll 1
    for (int p = 0; p < 2; ++p) {
        if ((nw >> 1) == p) {
#pragma unroll
            for (int mi = 0; mi < 2; ++mi)
#pragma unroll
                for (int ni = 0; ni < 4; ++ni)
#pragma unroll
                    for (int r = 0; r < 4; ++r) {
                        int tile_l = mw * 32 + mi * 16 + (lane >> 2) + ((r >= 2) ? 8 : 0);
                        int co_l = (nw & 1) * 32 + ni * 8 + 2 * (lane & 3) + (r & 1);
                        int base = co_l * (4 * EPI_PITCH)
                                 + (2 * (tile_l >> 5)) * EPI_PITCH + 2 * (tile_l & 31);
#pragma unroll
                        for (int pos = 0; pos < 4; ++pos)
                            smo[base + (pos >> 1) * EPI_PITCH + (pos & 1)] =
                                y[mi][ni][r][pos];
                    }
        }
        __syncthreads();
#pragma unroll 4
        for (int it = 0; it < 32; ++it) {
            int row = wid + 8 * it;               // 0..255 = 64co x 4h
            int co_f = row >> 2, h_f = row & 3;
            int cog = co0 + p * 64 + co_f;
            float dv = g_d[b * COUT + cog];
            float bv = bias[cog];
            int w = 2 * lane;
            int hg = h0 + h_f;
            float v0 = smo[co_f * (4 * EPI_PITCH) + h_f * EPI_PITCH + w];
            float v1 = smo[co_f * (4 * EPI_PITCH) + h_f * EPI_PITCH + w + 1];
            float nz0 = noise[(b * HH + hg) * WW + w] * nwv;
            float nz1 = noise[(b * HH + hg) * WW + w + 1] * nwv;
            v0 = v0 * dv + nz0 + bv;
            v1 = v1 * dv + nz1 + bv;
            v0 = (v0 >= 0.f ? v0 : 0.2f * v0) * 1.4142135623730951f;
            v1 = (v1 >= 0.f ? v1 : 0.2f * v1) * 1.4142135623730951f;
            float2 o2 = make_float2(v0, v1);
            *(float2*)&out[((size_t)(b * COUT + cog) * HH + hg) * WW + w] = o2;
        }
        __syncthreads();
    }
}

// ---------------------------------------------------------------------------
extern "C" void kernel_launch(void* const* d_in, const int* in_sizes, int n_in,
                              void* d_out, int out_size) {
    const float* x       = (const float*)d_in[0];
    const float* style   = (const float*)d_in[1];
    const float* noise   = (const float*)d_in[2];
    const float* weight  = (const float*)d_in[3];
    const float* style_w = (const float*)d_in[4];
    const float* style_b = (const float*)d_in[5];
    const float* bias    = (const float*)d_in[6];
    const float* nw      = (const float*)d_in[7];
    float* out = (float*)d_out;

    cudaFuncSetAttribute(vtrans_kernel,
                         cudaFuncAttributeMaxDynamicSharedMemorySize, VT_SMEM);
    cudaFuncSetAttribute(wino_gemm_kernel,
                         cudaFuncAttributeMaxDynamicSharedMemorySize, SMEM_REQ);

    compute_s_kernel<<<BB, CIN>>>(style, style_w, style_b);
    wino_w_kernel<<<COUT, CIN>>>(weight);
    compute_d_kernel<<<BB, COUT>>>();
    vtrans_kernel<<<BB * 32 * 8, 256, VT_SMEM>>>(x);
    wino_gemm_kernel<<<dim3(256, 2), 256, SMEM_REQ>>>(noise, bias, nw, out);
}